// round 16
// baseline (speedup 1.0000x reference)
#include <cuda_runtime.h>
#include <cuda_bf16.h>
#include <cuda_fp16.h>
#include <math.h>
#include <stdint.h>

// Problem constants
#define BATCH 4
#define SEQ   2048
#define DIM   2048
#define HEADS 16
#define HDIM  128
#define MTOK  (BATCH * SEQ)          // 8192 tokens
#define WSLOT ((size_t)DIM * DIM)    // one weight slot (fp16)
#define ASLOT ((size_t)MTOK * DIM)   // one activation slot (fp16)

// -------------------- scratch (device globals; no cudaMalloc allowed) ------
__device__ __align__(1024) __half g_v16[ASLOT];       // v projection, fp16
__device__ __align__(1024) __half g_q16[ASLOT];       // rmsnormed q (pre-scaled)
__device__ __align__(1024) __half g_k16[ASLOT];       // rmsnormed k
__device__ __align__(1024) __half g_a16[3 * ASLOT];   // fp16 activations q/k/v
__device__ __align__(1024) __half g_w16[4 * WSLOT];   // fp16 weights q/k/v/o

// ===========================================================================
// helpers
// ===========================================================================
__device__ __forceinline__ uint32_t smem_u32(const void* p) {
    uint32_t a;
    asm("{ .reg .u64 t; cvta.to.shared.u64 t, %1; cvt.u32.u64 %0, t; }"
        : "=r"(a) : "l"(p));
    return a;
}

__device__ __forceinline__ void cp_async16(uint32_t saddr, const void* gptr) {
    asm volatile("cp.async.cg.shared.global [%0], [%1], 16;"
                 :: "r"(saddr), "l"(gptr) : "memory");
}

__device__ __forceinline__ void ldsm4(uint32_t& r0, uint32_t& r1,
                                      uint32_t& r2, uint32_t& r3, uint32_t addr) {
    asm volatile("ldmatrix.sync.aligned.m8n8.x4.shared.b16 {%0,%1,%2,%3}, [%4];"
                 : "=r"(r0), "=r"(r1), "=r"(r2), "=r"(r3) : "r"(addr));
}

__device__ __forceinline__ void ldsm4t(uint32_t& r0, uint32_t& r1,
                                       uint32_t& r2, uint32_t& r3, uint32_t addr) {
    asm volatile("ldmatrix.sync.aligned.m8n8.x4.trans.shared.b16 {%0,%1,%2,%3}, [%4];"
                 : "=r"(r0), "=r"(r1), "=r"(r2), "=r"(r3) : "r"(addr));
}

__device__ __forceinline__ void mma_fp16(float* c, const uint32_t* a,
                                         uint32_t b0, uint32_t b1) {
    asm volatile(
        "mma.sync.aligned.m16n8k16.row.col.f32.f16.f16.f32 "
        "{%0,%1,%2,%3}, {%4,%5,%6,%7}, {%8,%9}, {%0,%1,%2,%3};"
        : "+f"(c[0]), "+f"(c[1]), "+f"(c[2]), "+f"(c[3])
        : "r"(a[0]), "r"(a[1]), "r"(a[2]), "r"(a[3]), "r"(b0), "r"(b1));
}

// ===========================================================================
// merged fp32 -> fp16 conversion: grid.y 0..3 = weights, 4..6 = activations
// ===========================================================================
__global__ void __launch_bounds__(256)
f2h_all_kernel(const float* __restrict__ w0, const float* __restrict__ w1,
               const float* __restrict__ w2, const float* __restrict__ w3,
               const float* __restrict__ a0, const float* __restrict__ a1,
               const float* __restrict__ a2,
               __half* __restrict__ outW, __half* __restrict__ outA)
{
    int z = blockIdx.y;
    const float* in;
    __half* o;
    if (z < 4) {
        if (blockIdx.x >= (DIM * DIM / 4) / 256) return;   // weights: 4096 blocks
        in = (z == 0) ? w0 : (z == 1) ? w1 : (z == 2) ? w2 : w3;
        o = outW + (size_t)z * WSLOT;
    } else {
        in = (z == 4) ? a0 : (z == 5) ? a1 : a2;
        o = outA + (size_t)(z - 4) * ASLOT;
    }
    int i = blockIdx.x * 256 + threadIdx.x;
    float4 v = ((const float4*)in)[i];
    __half2 a = __floats2half2_rn(v.x, v.y);
    __half2 b = __floats2half2_rn(v.z, v.w);
    ((__half2*)o)[2 * i]     = a;
    ((__half2*)o)[2 * i + 1] = b;
}

// ===========================================================================
// GEMM core: CTA 128(M) x 256(N), BK=64, 4 stages, 512 threads, 16 warps
// (2 rows x 8 cols), warp tile 64x32.
// ===========================================================================
#define BK       64
#define PITCHB   144
#define TILE_A   (128 * PITCHB)               // 18432
#define TILE_B   (256 * PITCHB)               // 36864
#define STAGE_B  (TILE_A + TILE_B)            // 55296
#define STAGES   4
#define NCHUNK   (DIM / BK)                   // 32
#define GEMM_SMEM (STAGES * STAGE_B)          // 221184
#define GT       512

#define GEMM_MAINLOOP(Abase, Bbase)                                           \
    auto load_tile = [&](int s, int c) {                                      \
        const uint32_t sa = sbase + s * STAGE_B;                              \
        const uint32_t sbuf = sa + TILE_A;                                    \
        _Pragma("unroll")                                                     \
        for (int i = 0; i < 2; i++) {                                         \
            int idx = tid + i * GT;                                           \
            int row = idx >> 3, cc = idx & 7;                                 \
            cp_async16(sa + row * PITCHB + cc * 16,                           \
                       (Abase) + (size_t)row * DIM + c * BK + cc * 8);        \
        }                                                                     \
        _Pragma("unroll")                                                     \
        for (int i = 0; i < 4; i++) {                                         \
            int idx = tid + i * GT;                                           \
            int row = idx >> 3, cc = idx & 7;                                 \
            cp_async16(sbuf + row * PITCHB + cc * 16,                         \
                       (Bbase) + (size_t)row * DIM + c * BK + cc * 8);        \
        }                                                                     \
        asm volatile("cp.async.commit_group;" ::: "memory");                  \
    };                                                                        \
    float acc[4][4][4];                                                       \
    _Pragma("unroll")                                                         \
    for (int mi = 0; mi < 4; mi++)                                            \
        _Pragma("unroll")                                                     \
        for (int ni = 0; ni < 4; ni++)                                        \
            _Pragma("unroll")                                                 \
            for (int r = 0; r < 4; r++) acc[mi][ni][r] = 0.f;                 \
    load_tile(0, 0);                                                          \
    load_tile(1, 1);                                                          \
    load_tile(2, 2);                                                          \
    const uint32_t arow = wm + (lane & 15);                                   \
    const uint32_t brow = wn + (lane & 15);                                   \
    const uint32_t koff = (lane >> 4) * 16;                                   \
    for (int c = 0; c < NCHUNK; c++) {                                        \
        const int s = c % STAGES;                                             \
        asm volatile("cp.async.wait_group 2;" ::: "memory");                  \
        __syncthreads();                                                      \
        const int y = c + 3;                                                  \
        if (y < NCHUNK) load_tile(y % STAGES, y);                             \
        else asm volatile("cp.async.commit_group;" ::: "memory");             \
        const uint32_t sa = sbase + s * STAGE_B + arow * PITCHB + koff;       \
        const uint32_t sb = sbase + s * STAGE_B + TILE_A + brow * PITCHB + koff; \
        _Pragma("unroll")                                                     \
        for (int ks = 0; ks < 4; ks++) {                                      \
            uint32_t a[4][4];                                                 \
            _Pragma("unroll")                                                 \
            for (int mi = 0; mi < 4; mi++)                                    \
                ldsm4(a[mi][0], a[mi][1], a[mi][2], a[mi][3],                 \
                      sa + mi * 16 * PITCHB + ks * 32);                       \
            uint32_t b[2][4];                                                 \
            _Pragma("unroll")                                                 \
            for (int nb = 0; nb < 2; nb++)                                    \
                ldsm4(b[nb][0], b[nb][1], b[nb][2], b[nb][3],                 \
                      sb + nb * 16 * PITCHB + ks * 32);                       \
            _Pragma("unroll")                                                 \
            for (int mi = 0; mi < 4; mi++)                                    \
                _Pragma("unroll")                                             \
                for (int ni = 0; ni < 4; ni++)                                \
                    mma_fp16(acc[mi][ni], a[mi],                              \
                             b[ni >> 1][ni & 1], b[ni >> 1][(ni & 1) + 2]);   \
        }                                                                     \
    }

// ---------------------------------------------------------------------------
// Fused QKV GEMM + per-head RMSNorm epilogue (unchanged from R14/R15).
// ---------------------------------------------------------------------------
__global__ void __launch_bounds__(GT, 1)
gemm_qkv_kernel(const __half* __restrict__ Aall, const __half* __restrict__ Ball,
                const float* __restrict__ bq, const float* __restrict__ bk,
                const float* __restrict__ bv,
                const float* __restrict__ qnw, const float* __restrict__ knw,
                __half* __restrict__ Cq, __half* __restrict__ Ck,
                __half* __restrict__ Cv, float qscale)
{
    extern __shared__ __align__(1024) char smem[];
    const uint32_t sbase = smem_u32(smem);
    const int tid  = threadIdx.x;
    const int lane = tid & 31;
    const int wid  = tid >> 5;
    const int wm   = (wid >> 3) * 64;
    const int wn   = (wid & 7) * 32;
    const int m0   = blockIdx.y * 128;
    const int region = blockIdx.x >> 3;
    const int n0   = blockIdx.x * 256;
    const int n0r  = (blockIdx.x & 7) * 256;

    const __half* Abase = Aall + (size_t)region * ASLOT + (size_t)m0 * DIM;
    const __half* Bbase = Ball + (size_t)n0 * DIM;

    GEMM_MAINLOOP(Abase, Bbase)

    const float* bias = (region == 0) ? bq : (region == 1) ? bk : bv;

    #pragma unroll
    for (int mi = 0; mi < 4; mi++)
        #pragma unroll
        for (int ni = 0; ni < 4; ni++) {
            const int col = n0r + wn + ni * 8 + (lane & 3) * 2;
            float b0 = bias[col], b1 = bias[col + 1];
            acc[mi][ni][0] += b0; acc[mi][ni][1] += b1;
            acc[mi][ni][2] += b0; acc[mi][ni][3] += b1;
        }

    if (region < 2) {
        __syncthreads();
        float* partial = (float*)smem;          // [8 warpcols][128 rows]

        float ss[4][2];
        #pragma unroll
        for (int mi = 0; mi < 4; mi++) {
            float s0 = 0.f, s1 = 0.f;
            #pragma unroll
            for (int ni = 0; ni < 4; ni++) {
                s0 += acc[mi][ni][0] * acc[mi][ni][0]
                    + acc[mi][ni][1] * acc[mi][ni][1];
                s1 += acc[mi][ni][2] * acc[mi][ni][2]
                    + acc[mi][ni][3] * acc[mi][ni][3];
            }
            s0 += __shfl_xor_sync(0xffffffffu, s0, 1);
            s0 += __shfl_xor_sync(0xffffffffu, s0, 2);
            s1 += __shfl_xor_sync(0xffffffffu, s1, 1);
            s1 += __shfl_xor_sync(0xffffffffu, s1, 2);
            ss[mi][0] = s0; ss[mi][1] = s1;
        }
        if ((lane & 3) == 0) {
            const int wc = wid & 7;
            #pragma unroll
            for (int mi = 0; mi < 4; mi++) {
                int row = wm + mi * 16 + (lane >> 2);
                partial[wc * 128 + row]     = ss[mi][0];
                partial[wc * 128 + row + 8] = ss[mi][1];
            }
        }
        __syncthreads();

        const float* nw = (region == 0) ? qnw : knw;
        const float outscale = (region == 0) ? qscale : 1.0f;
        __half* C = (region == 0) ? Cq : Ck;
        const int hg = (wn >> 7) << 2;

        #pragma unroll
        for (int mi = 0; mi < 4; mi++) {
            #pragma unroll
            for (int half = 0; half < 2; half++) {
                const int row = wm + mi * 16 + (lane >> 2) + half * 8;
                float sum = partial[(hg + 0) * 128 + row]
                          + partial[(hg + 1) * 128 + row]
                          + partial[(hg + 2) * 128 + row]
                          + partial[(hg + 3) * 128 + row];
                float r = rsqrtf(sum * (1.0f / 128.0f) + 1e-6f) * outscale;
                #pragma unroll
                for (int ni = 0; ni < 4; ni++) {
                    const int col = n0r + wn + ni * 8 + (lane & 3) * 2;
                    const int hc = col & 127;
                    __half2 v = __floats2half2_rn(
                        acc[mi][ni][half * 2]     * r * nw[hc],
                        acc[mi][ni][half * 2 + 1] * r * nw[hc + 1]);
                    *(__half2*)&C[(size_t)(m0 + row) * DIM + col] = v;
                }
            }
        }
    } else {
        #pragma unroll
        for (int mi = 0; mi < 4; mi++) {
            const int r = m0 + wm + mi * 16 + (lane >> 2);
            #pragma unroll
            for (int ni = 0; ni < 4; ni++) {
                const int col = n0r + wn + ni * 8 + (lane & 3) * 2;
                __half2 v0 = __floats2half2_rn(acc[mi][ni][0], acc[mi][ni][1]);
                __half2 v1 = __floats2half2_rn(acc[mi][ni][2], acc[mi][ni][3]);
                *(__half2*)&Cv[(size_t)r * DIM + col]       = v0;
                *(__half2*)&Cv[(size_t)(r + 8) * DIM + col] = v1;
            }
        }
    }
}

// ---------------------------------------------------------------------------
// Out-projection GEMM (fp32 output), same 512-thread core.
// ---------------------------------------------------------------------------
__global__ void __launch_bounds__(GT, 1)
gemm_mma_kernel(const __half* __restrict__ Ap, const __half* __restrict__ Bp,
                const float* __restrict__ bias, float* __restrict__ C, int N)
{
    extern __shared__ __align__(1024) char smem[];
    const uint32_t sbase = smem_u32(smem);
    const int tid  = threadIdx.x;
    const int lane = tid & 31;
    const int wid  = tid >> 5;
    const int wm   = (wid >> 3) * 64;
    const int wn   = (wid & 7) * 32;
    const int m0   = blockIdx.y * 128;
    const int n0   = blockIdx.x * 256;

    const __half* Abase = Ap + (size_t)m0 * DIM;
    const __half* Bbase = Bp + (size_t)n0 * DIM;

    GEMM_MAINLOOP(Abase, Bbase)

    #pragma unroll
    for (int mi = 0; mi < 4; mi++) {
        const int r = m0 + wm + mi * 16 + (lane >> 2);
        #pragma unroll
        for (int ni = 0; ni < 4; ni++) {
            const int col = n0 + wn + ni * 8 + (lane & 3) * 2;
            float2 v0, v1;
            v0.x = acc[mi][ni][0] + bias[col];
            v0.y = acc[mi][ni][1] + bias[col + 1];
            v1.x = acc[mi][ni][2] + bias[col];
            v1.y = acc[mi][ni][3] + bias[col + 1];
            *(float2*)&C[(size_t)r * N + col]       = v0;
            *(float2*)&C[(size_t)(r + 8) * N + col] = v1;
        }
    }
}

// ===========================================================================
// fp16 flash attention, double-buffered K/V, Q fragments register-resident.
// smem: Q (34816) + 2 stages x (K 17408 + V 17408) = 104448 B.
// ===========================================================================
#define QT   128
#define KT   64
#define APIT 272
#define SQ_OFF 0
#define KVSTG  (2 * KT * APIT)                // 34816 per stage pair
#define SK_OFF(s) (QT * APIT + (s) * KVSTG)
#define SV_OFF(s) (SK_OFF(s) + KT * APIT)
#define ATTN_SMEM (QT * APIT + 2 * KVSTG)     // 104448

__global__ void __launch_bounds__(256, 1)
attn_mma_kernel(const __half* __restrict__ Qg, const __half* __restrict__ Kg,
                const __half* __restrict__ Vg, __half* __restrict__ Og)
{
    extern __shared__ __align__(1024) char asmem[];
    const uint32_t sb = smem_u32(asmem);

    const int tid  = threadIdx.x;
    const int lane = tid & 31;
    const int wid  = tid >> 5;
    const int wm   = wid * 16;
    const int sq0  = blockIdx.x * QT;
    const int b    = blockIdx.y >> 4;
    const int h    = blockIdx.y & 15;

    const __half* Qb = Qg + (size_t)(b * SEQ + sq0) * DIM + h * HDIM;
    const __half* Kb = Kg + (size_t)b * SEQ * DIM + h * HDIM;
    const __half* Vb = Vg + (size_t)b * SEQ * DIM + h * HDIM;

    auto load_kv = [&](int s, int kt) {
        const __half* Kt = Kb + (size_t)(kt * KT) * DIM;
        const __half* Vt = Vb + (size_t)(kt * KT) * DIM;
        #pragma unroll
        for (int i = 0; i < 4; i++) {
            int idx = tid + i * 256;
            int row = idx >> 4;
            int c16 = idx & 15;
            cp_async16(sb + SK_OFF(s) + row * APIT + c16 * 16,
                       Kt + (size_t)row * DIM + c16 * 8);
            cp_async16(sb + SV_OFF(s) + row * APIT + c16 * 16,
                       Vt + (size_t)row * DIM + c16 * 8);
        }
        asm volatile("cp.async.commit_group;" ::: "memory");
    };

    // ---- stage kv tile 0 (group 0), then Q (group 1) ----
    load_kv(0, 0);
    #pragma unroll
    for (int i = 0; i < 8; i++) {
        int idx = tid + i * 256;
        int row = idx >> 4;
        int c16 = idx & 15;
        cp_async16(sb + SQ_OFF + row * APIT + c16 * 16,
                   Qb + (size_t)row * DIM + c16 * 8);
    }
    asm volatile("cp.async.commit_group;" ::: "memory");
    asm volatile("cp.async.wait_group 0;" ::: "memory");   // Q + kv0 ready
    __syncthreads();

    // ---- load Q fragments once into registers (invariant across kv tiles) --
    const uint32_t qoff = (wm + (lane & 15)) * APIT + (lane >> 4) * 16;
    uint32_t qf[8][4];
    #pragma unroll
    for (int ks = 0; ks < 8; ks++)
        ldsm4(qf[ks][0], qf[ks][1], qf[ks][2], qf[ks][3],
              sb + SQ_OFF + qoff + ks * 32);

    float Sf[8][4];
    float Of[16][4];
    #pragma unroll
    for (int j = 0; j < 16; j++)
        #pragma unroll
        for (int r = 0; r < 4; r++) Of[j][r] = 0.f;
    float m0 = -1e30f, m1 = -1e30f, l0 = 0.f, l1 = 0.f;

    const uint32_t boff = ((lane & 7) + ((lane >> 4) << 3)) * APIT + ((lane >> 3) & 1) * 16;
    const uint32_t voff = ((lane & 7) + ((lane >> 3) & 1) * 8) * APIT + (lane >> 4) * 16;

    for (int kt = 0; kt < SEQ / KT; kt++) {
        const int s = kt & 1;
        if (kt > 0) __syncthreads();   // buffer s^1 free (tile kt-1 computed)

        if (kt + 1 < SEQ / KT) load_kv(s ^ 1, kt + 1);
        else asm volatile("cp.async.commit_group;" ::: "memory");

        asm volatile("cp.async.wait_group 1;" ::: "memory");  // tile kt ready
        __syncthreads();

        // ---- S = Q.K^T single fp16 pass (k=128 over 8 steps) ----
        #pragma unroll
        for (int j = 0; j < 8; j++)
            #pragma unroll
            for (int r = 0; r < 4; r++) Sf[j][r] = 0.f;

        const uint32_t bbase = sb + SK_OFF(s) + boff;
        #pragma unroll
        for (int ks = 0; ks < 8; ks++) {
            #pragma unroll
            for (int g = 0; g < 4; g++) {
                uint32_t r0, r1, r2, r3;
                ldsm4(r0, r1, r2, r3, bbase + g * 16 * APIT + ks * 32);
                mma_fp16(Sf[2 * g],     qf[ks], r0, r1);
                mma_fp16(Sf[2 * g + 1], qf[ks], r2, r3);
            }
        }

        // ---- online softmax ----
        float rmax0 = -1e30f, rmax1 = -1e30f;
        #pragma unroll
        for (int j = 0; j < 8; j++) {
            rmax0 = fmaxf(rmax0, fmaxf(Sf[j][0], Sf[j][1]));
            rmax1 = fmaxf(rmax1, fmaxf(Sf[j][2], Sf[j][3]));
        }
        rmax0 = fmaxf(rmax0, __shfl_xor_sync(0xffffffffu, rmax0, 1));
        rmax0 = fmaxf(rmax0, __shfl_xor_sync(0xffffffffu, rmax0, 2));
        rmax1 = fmaxf(rmax1, __shfl_xor_sync(0xffffffffu, rmax1, 1));
        rmax1 = fmaxf(rmax1, __shfl_xor_sync(0xffffffffu, rmax1, 2));

        float mn0 = fmaxf(m0, rmax0);
        float mn1 = fmaxf(m1, rmax1);
        float al0 = __expf(m0 - mn0);
        float al1 = __expf(m1 - mn1);
        m0 = mn0; m1 = mn1;

        float rs0 = 0.f, rs1 = 0.f;
        uint32_t ph[8][2];
        #pragma unroll
        for (int j = 0; j < 8; j++) {
            float p0 = __expf(Sf[j][0] - m0);
            float p1 = __expf(Sf[j][1] - m0);
            float p2 = __expf(Sf[j][2] - m1);
            float p3 = __expf(Sf[j][3] - m1);
            rs0 += p0 + p1;
            rs1 += p2 + p3;
            __half2 h0 = __floats2half2_rn(p0, p1);
            __half2 h1 = __floats2half2_rn(p2, p3);
            ph[j][0] = *reinterpret_cast<uint32_t*>(&h0);
            ph[j][1] = *reinterpret_cast<uint32_t*>(&h1);
        }
        rs0 += __shfl_xor_sync(0xffffffffu, rs0, 1);
        rs0 += __shfl_xor_sync(0xffffffffu, rs0, 2);
        rs1 += __shfl_xor_sync(0xffffffffu, rs1, 1);
        rs1 += __shfl_xor_sync(0xffffffffu, rs1, 2);
        l0 = l0 * al0 + rs0;
        l1 = l1 * al1 + rs1;

        #pragma unroll
        for (int j = 0; j < 16; j++) {
            Of[j][0] *= al0; Of[j][1] *= al0;
            Of[j][2] *= al1; Of[j][3] *= al1;
        }

        // ---- O += P.V (single fp16 pass) ----
        const uint32_t vhb = sb + SV_OFF(s) + voff;
        #pragma unroll
        for (int ks = 0; ks < 4; ks++) {
            uint32_t pa[4] = { ph[2 * ks][0], ph[2 * ks][1],
                               ph[2 * ks + 1][0], ph[2 * ks + 1][1] };
            #pragma unroll
            for (int g = 0; g < 8; g++) {
                uint32_t v0, v1, v2, v3;
                ldsm4t(v0, v1, v2, v3, vhb + ks * 16 * APIT + g * 32);
                mma_fp16(Of[2 * g],     pa, v0, v1);
                mma_fp16(Of[2 * g + 1], pa, v2, v3);
            }
        }
    }

    // ---- normalize and store as fp16 (out-projection activation) ----
    const float inv0 = 1.0f / l0;
    const float inv1 = 1.0f / l1;
    const int r  = lane >> 2;
    const int c2 = (lane & 3) * 2;
    __half* Ob = Og + (size_t)(b * SEQ + sq0 + wm) * DIM + h * HDIM;
    #pragma unroll
    for (int j = 0; j < 16; j++) {
        const int col = j * 8 + c2;
        __half2 v0 = __floats2half2_rn(Of[j][0] * inv0, Of[j][1] * inv0);
        __half2 v1 = __floats2half2_rn(Of[j][2] * inv1, Of[j][3] * inv1);
        *(__half2*)&Ob[(size_t)r * DIM + col]       = v0;
        *(__half2*)&Ob[(size_t)(r + 8) * DIM + col] = v1;
    }
}

// ---------------------------------------------------------------------------
extern "C" void kernel_launch(void* const* d_in, const int* in_sizes, int n_in,
                              void* d_out, int out_size)
{
    const float* query = (const float*)d_in[0];
    const float* key   = (const float*)d_in[1];
    const float* value = (const float*)d_in[2];
    const float* Wq    = (const float*)d_in[3];
    const float* bq    = (const float*)d_in[4];
    const float* Wk    = (const float*)d_in[5];
    const float* bk    = (const float*)d_in[6];
    const float* Wv    = (const float*)d_in[7];
    const float* bv    = (const float*)d_in[8];
    const float* Wo    = (const float*)d_in[9];
    const float* bo    = (const float*)d_in[10];
    const float* qnw   = (const float*)d_in[11];
    const float* knw   = (const float*)d_in[12];
    float* out = (float*)d_out;

    __half *gv16, *gq16, *gk16, *ga16, *gw16;
    cudaGetSymbolAddress((void**)&gv16, g_v16);
    cudaGetSymbolAddress((void**)&gq16, g_q16);
    cudaGetSymbolAddress((void**)&gk16, g_k16);
    cudaGetSymbolAddress((void**)&ga16, g_a16);
    cudaGetSymbolAddress((void**)&gw16, g_w16);

    cudaFuncSetAttribute(gemm_qkv_kernel,
                         cudaFuncAttributeMaxDynamicSharedMemorySize, GEMM_SMEM);
    cudaFuncSetAttribute(gemm_mma_kernel,
                         cudaFuncAttributeMaxDynamicSharedMemorySize, GEMM_SMEM);
    cudaFuncSetAttribute(attn_mma_kernel,
                         cudaFuncAttributeMaxDynamicSharedMemorySize, ATTN_SMEM);

    // 1) convert weights + activations in one launch
    dim3 cgrid((MTOK * DIM / 4) / 256, 7);             // (16384, 7)
    f2h_all_kernel<<<cgrid, 256>>>(Wq, Wk, Wv, Wo, query, key, value,
                                   gw16, ga16);

    // 2) fused QKV projection + RMSNorm epilogue (one launch)
    dim3 qkv_grid(3 * DIM / 256, MTOK / 128);          // (24, 64)
    gemm_qkv_kernel<<<qkv_grid, GT, GEMM_SMEM>>>(ga16, gw16, bq, bk, bv,
                                                 qnw, knw, gq16, gk16, gv16,
                                                 0.08838834764831845f);

    // 3) attention (double-buffered K/V, Q in registers)
    dim3 attn_grid(SEQ / QT, BATCH * HEADS);           // (16, 64)
    attn_mma_kernel<<<attn_grid, 256, ATTN_SMEM>>>(gq16, gk16, gv16, ga16);

    // 4) output projection
    dim3 gemm_grid(DIM / 256, MTOK / 128);             // (8, 64)
    gemm_mma_kernel<<<gemm_grid, GT, GEMM_SMEM>>>(ga16, gw16 + 3 * WSLOT, bo, out, DIM);
}

// round 17
// speedup vs baseline: 1.0348x; 1.0348x over previous
#include <cuda_runtime.h>
#include <cuda_bf16.h>
#include <cuda_fp16.h>
#include <math.h>
#include <stdint.h>

// Problem constants
#define BATCH 4
#define SEQ   2048
#define DIM   2048
#define HEADS 16
#define HDIM  128
#define MTOK  (BATCH * SEQ)          // 8192 tokens
#define WSLOT ((size_t)DIM * DIM)    // one weight slot (fp16)
#define ASLOT ((size_t)MTOK * DIM)   // one activation slot (fp16)

// -------------------- scratch (device globals; no cudaMalloc allowed) ------
__device__ __align__(1024) __half g_v16[ASLOT];       // v projection, fp16
__device__ __align__(1024) __half g_q16[ASLOT];       // rmsnormed q (pre-scaled)
__device__ __align__(1024) __half g_k16[ASLOT];       // rmsnormed k
__device__ __align__(1024) __half g_a16[3 * ASLOT];   // fp16 activations q/k/v
__device__ __align__(1024) __half g_w16[4 * WSLOT];   // fp16 weights q/k/v/o

// ===========================================================================
// helpers
// ===========================================================================
__device__ __forceinline__ uint32_t smem_u32(const void* p) {
    uint32_t a;
    asm("{ .reg .u64 t; cvta.to.shared.u64 t, %1; cvt.u32.u64 %0, t; }"
        : "=r"(a) : "l"(p));
    return a;
}

__device__ __forceinline__ void cp_async16(uint32_t saddr, const void* gptr) {
    asm volatile("cp.async.cg.shared.global [%0], [%1], 16;"
                 :: "r"(saddr), "l"(gptr) : "memory");
}

__device__ __forceinline__ void ldsm4(uint32_t& r0, uint32_t& r1,
                                      uint32_t& r2, uint32_t& r3, uint32_t addr) {
    asm volatile("ldmatrix.sync.aligned.m8n8.x4.shared.b16 {%0,%1,%2,%3}, [%4];"
                 : "=r"(r0), "=r"(r1), "=r"(r2), "=r"(r3) : "r"(addr));
}

__device__ __forceinline__ void ldsm4t(uint32_t& r0, uint32_t& r1,
                                       uint32_t& r2, uint32_t& r3, uint32_t addr) {
    asm volatile("ldmatrix.sync.aligned.m8n8.x4.trans.shared.b16 {%0,%1,%2,%3}, [%4];"
                 : "=r"(r0), "=r"(r1), "=r"(r2), "=r"(r3) : "r"(addr));
}

__device__ __forceinline__ void mma_fp16(float* c, const uint32_t* a,
                                         uint32_t b0, uint32_t b1) {
    asm volatile(
        "mma.sync.aligned.m16n8k16.row.col.f32.f16.f16.f32 "
        "{%0,%1,%2,%3}, {%4,%5,%6,%7}, {%8,%9}, {%0,%1,%2,%3};"
        : "+f"(c[0]), "+f"(c[1]), "+f"(c[2]), "+f"(c[3])
        : "r"(a[0]), "r"(a[1]), "r"(a[2]), "r"(a[3]), "r"(b0), "r"(b1));
}

// ===========================================================================
// batched fp32 -> fp16 conversions (R15 config)
// ===========================================================================
__global__ void __launch_bounds__(256)
f2h_w4_kernel(const float* __restrict__ w0, const float* __restrict__ w1,
              const float* __restrict__ w2, const float* __restrict__ w3,
              __half* __restrict__ out)
{
    int z = blockIdx.y;
    const float* in = (z == 0) ? w0 : (z == 1) ? w1 : (z == 2) ? w2 : w3;
    __half* o = out + (size_t)z * WSLOT;
    int i = blockIdx.x * 256 + threadIdx.x;
    float4 v = ((const float4*)in)[i];
    __half2 a = __floats2half2_rn(v.x, v.y);
    __half2 b = __floats2half2_rn(v.z, v.w);
    ((__half2*)o)[2 * i]     = a;
    ((__half2*)o)[2 * i + 1] = b;
}

__global__ void __launch_bounds__(256)
f2h_a3_kernel(const float* __restrict__ a0, const float* __restrict__ a1,
              const float* __restrict__ a2, __half* __restrict__ out)
{
    int z = blockIdx.y;
    const float* in = (z == 0) ? a0 : (z == 1) ? a1 : a2;
    __half* o = out + (size_t)z * ASLOT;
    int i = blockIdx.x * 256 + threadIdx.x;
    float4 v = ((const float4*)in)[i];
    __half2 a = __floats2half2_rn(v.x, v.y);
    __half2 b = __floats2half2_rn(v.z, v.w);
    ((__half2*)o)[2 * i]     = a;
    ((__half2*)o)[2 * i + 1] = b;
}

// ===========================================================================
// GEMM core: CTA 128(M) x 256(N), BK=64, 4 stages, 512 threads, 16 warps
// (2 rows x 8 cols), warp tile 64x32.
// ===========================================================================
#define BK       64
#define PITCHB   144
#define TILE_A   (128 * PITCHB)               // 18432
#define TILE_B   (256 * PITCHB)               // 36864
#define STAGE_B  (TILE_A + TILE_B)            // 55296
#define STAGES   4
#define NCHUNK   (DIM / BK)                   // 32
#define GEMM_SMEM (STAGES * STAGE_B)          // 221184
#define GT       512

#define GEMM_MAINLOOP(Abase, Bbase)                                           \
    auto load_tile = [&](int s, int c) {                                      \
        const uint32_t sa = sbase + s * STAGE_B;                              \
        const uint32_t sbuf = sa + TILE_A;                                    \
        _Pragma("unroll")                                                     \
        for (int i = 0; i < 2; i++) {                                         \
            int idx = tid + i * GT;                                           \
            int row = idx >> 3, cc = idx & 7;                                 \
            cp_async16(sa + row * PITCHB + cc * 16,                           \
                       (Abase) + (size_t)row * DIM + c * BK + cc * 8);        \
        }                                                                     \
        _Pragma("unroll")                                                     \
        for (int i = 0; i < 4; i++) {                                         \
            int idx = tid + i * GT;                                           \
            int row = idx >> 3, cc = idx & 7;                                 \
            cp_async16(sbuf + row * PITCHB + cc * 16,                         \
                       (Bbase) + (size_t)row * DIM + c * BK + cc * 8);        \
        }                                                                     \
        asm volatile("cp.async.commit_group;" ::: "memory");                  \
    };                                                                        \
    float acc[4][4][4];                                                       \
    _Pragma("unroll")                                                         \
    for (int mi = 0; mi < 4; mi++)                                            \
        _Pragma("unroll")                                                     \
        for (int ni = 0; ni < 4; ni++)                                        \
            _Pragma("unroll")                                                 \
            for (int r = 0; r < 4; r++) acc[mi][ni][r] = 0.f;                 \
    load_tile(0, 0);                                                          \
    load_tile(1, 1);                                                          \
    load_tile(2, 2);                                                          \
    const uint32_t arow = wm + (lane & 15);                                   \
    const uint32_t brow = wn + (lane & 15);                                   \
    const uint32_t koff = (lane >> 4) * 16;                                   \
    for (int c = 0; c < NCHUNK; c++) {                                        \
        const int s = c % STAGES;                                             \
        asm volatile("cp.async.wait_group 2;" ::: "memory");                  \
        __syncthreads();                                                      \
        const int y = c + 3;                                                  \
        if (y < NCHUNK) load_tile(y % STAGES, y);                             \
        else asm volatile("cp.async.commit_group;" ::: "memory");             \
        const uint32_t sa = sbase + s * STAGE_B + arow * PITCHB + koff;       \
        const uint32_t sb = sbase + s * STAGE_B + TILE_A + brow * PITCHB + koff; \
        _Pragma("unroll")                                                     \
        for (int ks = 0; ks < 4; ks++) {                                      \
            uint32_t a[4][4];                                                 \
            _Pragma("unroll")                                                 \
            for (int mi = 0; mi < 4; mi++)                                    \
                ldsm4(a[mi][0], a[mi][1], a[mi][2], a[mi][3],                 \
                      sa + mi * 16 * PITCHB + ks * 32);                       \
            uint32_t b[2][4];                                                 \
            _Pragma("unroll")                                                 \
            for (int nb = 0; nb < 2; nb++)                                    \
                ldsm4(b[nb][0], b[nb][1], b[nb][2], b[nb][3],                 \
                      sb + nb * 16 * PITCHB + ks * 32);                       \
            _Pragma("unroll")                                                 \
            for (int mi = 0; mi < 4; mi++)                                    \
                _Pragma("unroll")                                             \
                for (int ni = 0; ni < 4; ni++)                                \
                    mma_fp16(acc[mi][ni], a[mi],                              \
                             b[ni >> 1][ni & 1], b[ni >> 1][(ni & 1) + 2]);   \
        }                                                                     \
    }

// ---------------------------------------------------------------------------
// Fused QKV GEMM + per-head RMSNorm epilogue (unchanged).
// ---------------------------------------------------------------------------
__global__ void __launch_bounds__(GT, 1)
gemm_qkv_kernel(const __half* __restrict__ Aall, const __half* __restrict__ Ball,
                const float* __restrict__ bq, const float* __restrict__ bk,
                const float* __restrict__ bv,
                const float* __restrict__ qnw, const float* __restrict__ knw,
                __half* __restrict__ Cq, __half* __restrict__ Ck,
                __half* __restrict__ Cv, float qscale)
{
    extern __shared__ __align__(1024) char smem[];
    const uint32_t sbase = smem_u32(smem);
    const int tid  = threadIdx.x;
    const int lane = tid & 31;
    const int wid  = tid >> 5;
    const int wm   = (wid >> 3) * 64;
    const int wn   = (wid & 7) * 32;
    const int m0   = blockIdx.y * 128;
    const int region = blockIdx.x >> 3;
    const int n0   = blockIdx.x * 256;
    const int n0r  = (blockIdx.x & 7) * 256;

    const __half* Abase = Aall + (size_t)region * ASLOT + (size_t)m0 * DIM;
    const __half* Bbase = Ball + (size_t)n0 * DIM;

    GEMM_MAINLOOP(Abase, Bbase)

    const float* bias = (region == 0) ? bq : (region == 1) ? bk : bv;

    #pragma unroll
    for (int mi = 0; mi < 4; mi++)
        #pragma unroll
        for (int ni = 0; ni < 4; ni++) {
            const int col = n0r + wn + ni * 8 + (lane & 3) * 2;
            float b0 = bias[col], b1 = bias[col + 1];
            acc[mi][ni][0] += b0; acc[mi][ni][1] += b1;
            acc[mi][ni][2] += b0; acc[mi][ni][3] += b1;
        }

    if (region < 2) {
        __syncthreads();
        float* partial = (float*)smem;          // [8 warpcols][128 rows]

        float ss[4][2];
        #pragma unroll
        for (int mi = 0; mi < 4; mi++) {
            float s0 = 0.f, s1 = 0.f;
            #pragma unroll
            for (int ni = 0; ni < 4; ni++) {
                s0 += acc[mi][ni][0] * acc[mi][ni][0]
                    + acc[mi][ni][1] * acc[mi][ni][1];
                s1 += acc[mi][ni][2] * acc[mi][ni][2]
                    + acc[mi][ni][3] * acc[mi][ni][3];
            }
            s0 += __shfl_xor_sync(0xffffffffu, s0, 1);
            s0 += __shfl_xor_sync(0xffffffffu, s0, 2);
            s1 += __shfl_xor_sync(0xffffffffu, s1, 1);
            s1 += __shfl_xor_sync(0xffffffffu, s1, 2);
            ss[mi][0] = s0; ss[mi][1] = s1;
        }
        if ((lane & 3) == 0) {
            const int wc = wid & 7;
            #pragma unroll
            for (int mi = 0; mi < 4; mi++) {
                int row = wm + mi * 16 + (lane >> 2);
                partial[wc * 128 + row]     = ss[mi][0];
                partial[wc * 128 + row + 8] = ss[mi][1];
            }
        }
        __syncthreads();

        const float* nw = (region == 0) ? qnw : knw;
        const float outscale = (region == 0) ? qscale : 1.0f;
        __half* C = (region == 0) ? Cq : Ck;
        const int hg = (wn >> 7) << 2;

        #pragma unroll
        for (int mi = 0; mi < 4; mi++) {
            #pragma unroll
            for (int half = 0; half < 2; half++) {
                const int row = wm + mi * 16 + (lane >> 2) + half * 8;
                float sum = partial[(hg + 0) * 128 + row]
                          + partial[(hg + 1) * 128 + row]
                          + partial[(hg + 2) * 128 + row]
                          + partial[(hg + 3) * 128 + row];
                float r = rsqrtf(sum * (1.0f / 128.0f) + 1e-6f) * outscale;
                #pragma unroll
                for (int ni = 0; ni < 4; ni++) {
                    const int col = n0r + wn + ni * 8 + (lane & 3) * 2;
                    const int hc = col & 127;
                    __half2 v = __floats2half2_rn(
                        acc[mi][ni][half * 2]     * r * nw[hc],
                        acc[mi][ni][half * 2 + 1] * r * nw[hc + 1]);
                    *(__half2*)&C[(size_t)(m0 + row) * DIM + col] = v;
                }
            }
        }
    } else {
        #pragma unroll
        for (int mi = 0; mi < 4; mi++) {
            const int r = m0 + wm + mi * 16 + (lane >> 2);
            #pragma unroll
            for (int ni = 0; ni < 4; ni++) {
                const int col = n0r + wn + ni * 8 + (lane & 3) * 2;
                __half2 v0 = __floats2half2_rn(acc[mi][ni][0], acc[mi][ni][1]);
                __half2 v1 = __floats2half2_rn(acc[mi][ni][2], acc[mi][ni][3]);
                *(__half2*)&Cv[(size_t)r * DIM + col]       = v0;
                *(__half2*)&Cv[(size_t)(r + 8) * DIM + col] = v1;
            }
        }
    }
}

// ---------------------------------------------------------------------------
// Out-projection GEMM (fp32 output), same 512-thread core.
// ---------------------------------------------------------------------------
__global__ void __launch_bounds__(GT, 1)
gemm_mma_kernel(const __half* __restrict__ Ap, const __half* __restrict__ Bp,
                const float* __restrict__ bias, float* __restrict__ C, int N)
{
    extern __shared__ __align__(1024) char smem[];
    const uint32_t sbase = smem_u32(smem);
    const int tid  = threadIdx.x;
    const int lane = tid & 31;
    const int wid  = tid >> 5;
    const int wm   = (wid >> 3) * 64;
    const int wn   = (wid & 7) * 32;
    const int m0   = blockIdx.y * 128;
    const int n0   = blockIdx.x * 256;

    const __half* Abase = Ap + (size_t)m0 * DIM;
    const __half* Bbase = Bp + (size_t)n0 * DIM;

    GEMM_MAINLOOP(Abase, Bbase)

    #pragma unroll
    for (int mi = 0; mi < 4; mi++) {
        const int r = m0 + wm + mi * 16 + (lane >> 2);
        #pragma unroll
        for (int ni = 0; ni < 4; ni++) {
            const int col = n0 + wn + ni * 8 + (lane & 3) * 2;
            float2 v0, v1;
            v0.x = acc[mi][ni][0] + bias[col];
            v0.y = acc[mi][ni][1] + bias[col + 1];
            v1.x = acc[mi][ni][2] + bias[col];
            v1.y = acc[mi][ni][3] + bias[col + 1];
            *(float2*)&C[(size_t)r * N + col]       = v0;
            *(float2*)&C[(size_t)(r + 8) * N + col] = v1;
        }
    }
}

// ===========================================================================
// fp16 flash attention: KT=128 kv-tiles (16 tiles), double-buffered.
// smem: Q (34816) + 2 stages x (K 34816 + V 34816) = 174080 B.
// Halves per-tile fixed costs (shuffle reduces, O rescale, barriers, Q ldsm).
// ===========================================================================
#define QT   128
#define KT2  128
#define APIT 272
#define SQ_OFF 0
#define KVSTG  (2 * KT2 * APIT)               // 69632 per stage pair
#define SK_OFF(s) (QT * APIT + (s) * KVSTG)
#define SV_OFF(s) (SK_OFF(s) + KT2 * APIT)
#define ATTN_SMEM (QT * APIT + 2 * KVSTG)     // 174080

__global__ void __launch_bounds__(256, 1)
attn_mma_kernel(const __half* __restrict__ Qg, const __half* __restrict__ Kg,
                const __half* __restrict__ Vg, __half* __restrict__ Og)
{
    extern __shared__ __align__(1024) char asmem[];
    const uint32_t sb = smem_u32(asmem);

    const int tid  = threadIdx.x;
    const int lane = tid & 31;
    const int wid  = tid >> 5;
    const int wm   = wid * 16;
    const int sq0  = blockIdx.x * QT;
    const int b    = blockIdx.y >> 4;
    const int h    = blockIdx.y & 15;

    const __half* Qb = Qg + (size_t)(b * SEQ + sq0) * DIM + h * HDIM;
    const __half* Kb = Kg + (size_t)b * SEQ * DIM + h * HDIM;
    const __half* Vb = Vg + (size_t)b * SEQ * DIM + h * HDIM;

    // loader for one 128-row K/V tile into stage s
    auto load_kv = [&](int s, int kt) {
        const __half* Kt = Kb + (size_t)(kt * KT2) * DIM;
        const __half* Vt = Vb + (size_t)(kt * KT2) * DIM;
        #pragma unroll
        for (int i = 0; i < 8; i++) {
            int idx = tid + i * 256;
            int row = idx >> 4;
            int c16 = idx & 15;
            cp_async16(sb + SK_OFF(s) + row * APIT + c16 * 16,
                       Kt + (size_t)row * DIM + c16 * 8);
            cp_async16(sb + SV_OFF(s) + row * APIT + c16 * 16,
                       Vt + (size_t)row * DIM + c16 * 8);
        }
        asm volatile("cp.async.commit_group;" ::: "memory");
    };

    // ---- stage Q + first K/V tile (one group) ----
    #pragma unroll
    for (int i = 0; i < 8; i++) {
        int idx = tid + i * 256;
        int row = idx >> 4;
        int c16 = idx & 15;
        cp_async16(sb + SQ_OFF + row * APIT + c16 * 16,
                   Qb + (size_t)row * DIM + c16 * 8);
    }
    load_kv(0, 0);   // commit includes Q loads issued above

    float Sf[16][4];
    float Of[16][4];
    #pragma unroll
    for (int j = 0; j < 16; j++)
        #pragma unroll
        for (int r = 0; r < 4; r++) Of[j][r] = 0.f;
    float m0 = -1e30f, m1 = -1e30f, l0 = 0.f, l1 = 0.f;

    const uint32_t qoff = (wm + (lane & 15)) * APIT + (lane >> 4) * 16;
    const uint32_t boff = ((lane & 7) + ((lane >> 4) << 3)) * APIT + ((lane >> 3) & 1) * 16;
    const uint32_t voff = ((lane & 7) + ((lane >> 3) & 1) * 8) * APIT + (lane >> 4) * 16;
    const uint32_t abase = sb + SQ_OFF + qoff;

    for (int kt = 0; kt < SEQ / KT2; kt++) {
        const int s = kt & 1;
        if (kt > 0) __syncthreads();   // buffer s^1 free (tile kt-1 computed)

        if (kt + 1 < SEQ / KT2) load_kv(s ^ 1, kt + 1);
        else asm volatile("cp.async.commit_group;" ::: "memory");

        asm volatile("cp.async.wait_group 1;" ::: "memory");  // tile kt ready
        __syncthreads();

        // ---- S = Q.K^T (128 q rows x 128 keys; warp: 16 x 128) ----
        #pragma unroll
        for (int j = 0; j < 16; j++)
            #pragma unroll
            for (int r = 0; r < 4; r++) Sf[j][r] = 0.f;

        const uint32_t bbase = sb + SK_OFF(s) + boff;
        #pragma unroll
        for (int ks = 0; ks < 8; ks++) {
            uint32_t a[4];
            ldsm4(a[0], a[1], a[2], a[3], abase + ks * 32);
            #pragma unroll
            for (int g = 0; g < 8; g++) {
                uint32_t r0, r1, r2, r3;
                ldsm4(r0, r1, r2, r3, bbase + g * 16 * APIT + ks * 32);
                mma_fp16(Sf[2 * g],     a, r0, r1);
                mma_fp16(Sf[2 * g + 1], a, r2, r3);
            }
        }

        // ---- online softmax ----
        float rmax0 = -1e30f, rmax1 = -1e30f;
        #pragma unroll
        for (int j = 0; j < 16; j++) {
            rmax0 = fmaxf(rmax0, fmaxf(Sf[j][0], Sf[j][1]));
            rmax1 = fmaxf(rmax1, fmaxf(Sf[j][2], Sf[j][3]));
        }
        rmax0 = fmaxf(rmax0, __shfl_xor_sync(0xffffffffu, rmax0, 1));
        rmax0 = fmaxf(rmax0, __shfl_xor_sync(0xffffffffu, rmax0, 2));
        rmax1 = fmaxf(rmax1, __shfl_xor_sync(0xffffffffu, rmax1, 1));
        rmax1 = fmaxf(rmax1, __shfl_xor_sync(0xffffffffu, rmax1, 2));

        float mn0 = fmaxf(m0, rmax0);
        float mn1 = fmaxf(m1, rmax1);
        float al0 = __expf(m0 - mn0);
        float al1 = __expf(m1 - mn1);
        m0 = mn0; m1 = mn1;

        float rs0 = 0.f, rs1 = 0.f;
        uint32_t ph[16][2];
        #pragma unroll
        for (int j = 0; j < 16; j++) {
            float p0 = __expf(Sf[j][0] - m0);
            float p1 = __expf(Sf[j][1] - m0);
            float p2 = __expf(Sf[j][2] - m1);
            float p3 = __expf(Sf[j][3] - m1);
            rs0 += p0 + p1;
            rs1 += p2 + p3;
            __half2 h0 = __floats2half2_rn(p0, p1);
            __half2 h1 = __floats2half2_rn(p2, p3);
            ph[j][0] = *reinterpret_cast<uint32_t*>(&h0);
            ph[j][1] = *reinterpret_cast<uint32_t*>(&h1);
        }
        rs0 += __shfl_xor_sync(0xffffffffu, rs0, 1);
        rs0 += __shfl_xor_sync(0xffffffffu, rs0, 2);
        rs1 += __shfl_xor_sync(0xffffffffu, rs1, 1);
        rs1 += __shfl_xor_sync(0xffffffffu, rs1, 2);
        l0 = l0 * al0 + rs0;
        l1 = l1 * al1 + rs1;

        #pragma unroll
        for (int j = 0; j < 16; j++) {
            Of[j][0] *= al0; Of[j][1] *= al0;
            Of[j][2] *= al1; Of[j][3] *= al1;
        }

        // ---- O += P.V (128 keys over 8 k-steps of 16) ----
        const uint32_t vhb = sb + SV_OFF(s) + voff;
        #pragma unroll
        for (int ks = 0; ks < 8; ks++) {
            uint32_t pa[4] = { ph[2 * ks][0], ph[2 * ks][1],
                               ph[2 * ks + 1][0], ph[2 * ks + 1][1] };
            #pragma unroll
            for (int g = 0; g < 8; g++) {
                uint32_t v0, v1, v2, v3;
                ldsm4t(v0, v1, v2, v3, vhb + ks * 16 * APIT + g * 32);
                mma_fp16(Of[2 * g],     pa, v0, v1);
                mma_fp16(Of[2 * g + 1], pa, v2, v3);
            }
        }
    }

    // ---- normalize and store as fp16 (out-projection activation) ----
    const float inv0 = 1.0f / l0;
    const float inv1 = 1.0f / l1;
    const int r  = lane >> 2;
    const int c2 = (lane & 3) * 2;
    __half* Ob = Og + (size_t)(b * SEQ + sq0 + wm) * DIM + h * HDIM;
    #pragma unroll
    for (int j = 0; j < 16; j++) {
        const int col = j * 8 + c2;
        __half2 v0 = __floats2half2_rn(Of[j][0] * inv0, Of[j][1] * inv0);
        __half2 v1 = __floats2half2_rn(Of[j][2] * inv1, Of[j][3] * inv1);
        *(__half2*)&Ob[(size_t)r * DIM + col]       = v0;
        *(__half2*)&Ob[(size_t)(r + 8) * DIM + col] = v1;
    }
}

// ---------------------------------------------------------------------------
extern "C" void kernel_launch(void* const* d_in, const int* in_sizes, int n_in,
                              void* d_out, int out_size)
{
    const float* query = (const float*)d_in[0];
    const float* key   = (const float*)d_in[1];
    const float* value = (const float*)d_in[2];
    const float* Wq    = (const float*)d_in[3];
    const float* bq    = (const float*)d_in[4];
    const float* Wk    = (const float*)d_in[5];
    const float* bk    = (const float*)d_in[6];
    const float* Wv    = (const float*)d_in[7];
    const float* bv    = (const float*)d_in[8];
    const float* Wo    = (const float*)d_in[9];
    const float* bo    = (const float*)d_in[10];
    const float* qnw   = (const float*)d_in[11];
    const float* knw   = (const float*)d_in[12];
    float* out = (float*)d_out;

    __half *gv16, *gq16, *gk16, *ga16, *gw16;
    cudaGetSymbolAddress((void**)&gv16, g_v16);
    cudaGetSymbolAddress((void**)&gq16, g_q16);
    cudaGetSymbolAddress((void**)&gk16, g_k16);
    cudaGetSymbolAddress((void**)&ga16, g_a16);
    cudaGetSymbolAddress((void**)&gw16, g_w16);

    cudaFuncSetAttribute(gemm_qkv_kernel,
                         cudaFuncAttributeMaxDynamicSharedMemorySize, GEMM_SMEM);
    cudaFuncSetAttribute(gemm_mma_kernel,
                         cudaFuncAttributeMaxDynamicSharedMemorySize, GEMM_SMEM);
    cudaFuncSetAttribute(attn_mma_kernel,
                         cudaFuncAttributeMaxDynamicSharedMemorySize, ATTN_SMEM);

    // 1) convert all weights + all activations (2 launches)
    dim3 wgrid((DIM * DIM / 4) / 256, 4);              // (4096, 4)
    f2h_w4_kernel<<<wgrid, 256>>>(Wq, Wk, Wv, Wo, gw16);
    dim3 agrid((MTOK * DIM / 4) / 256, 3);             // (16384, 3)
    f2h_a3_kernel<<<agrid, 256>>>(query, key, value, ga16);

    // 2) fused QKV projection + RMSNorm epilogue (one launch)
    dim3 qkv_grid(3 * DIM / 256, MTOK / 128);          // (24, 64)
    gemm_qkv_kernel<<<qkv_grid, GT, GEMM_SMEM>>>(ga16, gw16, bq, bk, bv,
                                                 qnw, knw, gq16, gk16, gv16,
                                                 0.08838834764831845f);

    // 3) attention (KT=128 double-buffered)
    dim3 attn_grid(SEQ / QT, BATCH * HEADS);           // (16, 64)
    attn_mma_kernel<<<attn_grid, 256, ATTN_SMEM>>>(gq16, gk16, gv16, ga16);

    // 4) output projection
    dim3 gemm_grid(DIM / 256, MTOK / 128);             // (8, 64)
    gemm_mma_kernel<<<gemm_grid, GT, GEMM_SMEM>>>(ga16, gw16 + 3 * WSLOT, bo, out, DIM);
}